// round 3
// baseline (speedup 1.0000x reference)
#include <cuda_runtime.h>
#include <cstdint>

// Skeleton FK: angles [B,24,6] f32, xyz [1,24,3] f32 -> out [B,24,3] f32
//
// 4 warps/block, warp = role, lane = batch row (32 rows/CTA).
//   A: root(store) + 1,4,7,10 ; re-root + 2,5,8,11
//   B: root + 3,6,9 (store) + 12,15
//   C: root + 3,6,9 (recompute) + 13,16,18,20,22
//   D: root + 3,6,9 (recompute) + 14,17,19,21,23
// Output T_c overwrites joint c's angle slot (c*6) in smem, EXCEPT joints
// {0,3,6,9} (read by multiple warps) which go to a 12-float side region at
// row offset 144+c. Row = 157 floats (odd stride -> conflict-free banks).

#define TPB  128
#define ROWS 32
#define RROW 157
#define XOFF_SZ 76

__constant__ int c_parent[24] = {-1, 0, 0, 0, 1, 2, 3, 4, 5, 6, 7, 8,
                                  9, 9, 9, 12, 13, 14, 16, 17, 18, 19, 20, 21};

__device__ __forceinline__ void rot6d(const float* __restrict__ s, float R[9]) {
    float a1x = s[0], a1y = s[1], a1z = s[2];
    float a2x = s[3], a2y = s[4], a2z = s[5];
    float inv1 = rsqrtf(fmaf(a1x, a1x, fmaf(a1y, a1y, a1z * a1z)));
    float b1x = a1x * inv1, b1y = a1y * inv1, b1z = a1z * inv1;
    float d = fmaf(b1x, a2x, fmaf(b1y, a2y, b1z * a2z));
    float c2x = fmaf(-d, b1x, a2x);
    float c2y = fmaf(-d, b1y, a2y);
    float c2z = fmaf(-d, b1z, a2z);
    float inv2 = rsqrtf(fmaf(c2x, c2x, fmaf(c2y, c2y, c2z * c2z)));
    float b2x = c2x * inv2, b2y = c2y * inv2, b2z = c2z * inv2;
    float b3x = fmaf(b1y, b2z, -b1z * b2y);
    float b3y = fmaf(b1z, b2x, -b1x * b2z);
    float b3z = fmaf(b1x, b2y, -b1y * b2x);
    R[0] = b1x; R[1] = b1y; R[2] = b1z;
    R[3] = b2x; R[4] = b2y; R[5] = b2z;
    R[6] = b3x; R[7] = b3y; R[8] = b3z;
}

// Root: R = rot6d(angles[0]), T = R @ xyz0. store -> side slot 144.
__device__ __forceinline__ void fk_root(float* __restrict__ srow,
                                        const float* __restrict__ xoff,
                                        float R[9], float T[3], bool store) {
    rot6d(srow, R);
    float rx = xoff[0], ry = xoff[1], rz = xoff[2];
    T[0] = fmaf(R[0], rx, fmaf(R[1], ry, R[2] * rz));
    T[1] = fmaf(R[3], rx, fmaf(R[4], ry, R[5] * rz));
    T[2] = fmaf(R[6], rx, fmaf(R[7], ry, R[8] * rz));
    if (store) { srow[144] = T[0]; srow[145] = T[1]; srow[146] = T[2]; }
}

// One FK step for child joint c (compile-time constant after inlining).
// store: true -> write T to its output slot (in-place or side for 3,6,9).
__device__ __forceinline__ void fk_step(float* __restrict__ srow,
                                        const float* __restrict__ xoff,
                                        int c, float R[9], float T[3],
                                        bool store) {
    float rc[9];
    rot6d(srow + c * 6, rc);
    float ox = xoff[c * 3 + 0], oy = xoff[c * 3 + 1], oz = xoff[c * 3 + 2];
    float t3x = fmaf(rc[0], ox, fmaf(rc[1], oy, rc[2] * oz));
    float t3y = fmaf(rc[3], ox, fmaf(rc[4], oy, rc[5] * oz));
    float t3z = fmaf(rc[6], ox, fmaf(rc[7], oy, rc[8] * oz));
    float Tn0 = fmaf(R[0], t3x, fmaf(R[1], t3y, fmaf(R[2], t3z, T[0])));
    float Tn1 = fmaf(R[3], t3x, fmaf(R[4], t3y, fmaf(R[5], t3z, T[1])));
    float Tn2 = fmaf(R[6], t3x, fmaf(R[7], t3y, fmaf(R[8], t3z, T[2])));
    float Rn[9];
#pragma unroll
    for (int r = 0; r < 3; r++)
#pragma unroll
        for (int k = 0; k < 3; k++)
            Rn[r * 3 + k] = fmaf(R[r * 3 + 0], rc[k],
                            fmaf(R[r * 3 + 1], rc[3 + k],
                                 R[r * 3 + 2] * rc[6 + k]));
#pragma unroll
    for (int i = 0; i < 9; i++) R[i] = Rn[i];
    T[0] = Tn0; T[1] = Tn1; T[2] = Tn2;
    if (store) {
        // joints 3,6,9 -> side slot 144+c; others in-place at c*6
        int base = (c <= 9 && (c % 3) == 0) ? (144 + c) : (c * 6);
        srow[base + 0] = Tn0;
        srow[base + 1] = Tn1;
        srow[base + 2] = Tn2;
    }
}

__global__ __launch_bounds__(TPB, 10) void skeleton_fk_kernel(
    const float* __restrict__ angles,
    const float* __restrict__ xyz,
    float* __restrict__ out,
    int B)
{
    __shared__ float sm[XOFF_SZ + ROWS * RROW];
    float* xoff = sm;
    float* rows = sm + XOFF_SZ;

    const int t    = threadIdx.x;
    const int wid  = t >> 5;
    const int lane = t & 31;
    const int b0   = blockIdx.x * ROWS;
    const int nvalid = min(ROWS, B - b0);

    // ---- bone offsets (root slot = absolute root pos) ----
    if (t < 24) {
        int p = c_parent[t];
        float x = __ldg(xyz + t * 3 + 0);
        float y = __ldg(xyz + t * 3 + 1);
        float z = __ldg(xyz + t * 3 + 2);
        if (p >= 0) {
            x -= __ldg(xyz + p * 3 + 0);
            y -= __ldg(xyz + p * 3 + 1);
            z -= __ldg(xyz + p * 3 + 2);
        }
        xoff[t * 3 + 0] = x;
        xoff[t * 3 + 1] = y;
        xoff[t * 3 + 2] = z;
    }

    // ---- coalesced load: 32 rows x 36 float4 ----
    {
        const float4* __restrict__ g4 =
            reinterpret_cast<const float4*>(angles) + (size_t)b0 * 36;
        const int total4 = nvalid * 36;
#pragma unroll
        for (int it = 0; it < 9; it++) {
            int idx = it * TPB + t;
            if (idx < total4) {
                float4 v = g4[idx];
                int row  = idx / 36;
                int col4 = idx % 36;
                float* dst = rows + row * RROW + col4 * 4;
                dst[0] = v.x; dst[1] = v.y; dst[2] = v.z; dst[3] = v.w;
            }
        }
    }
    __syncthreads();

    // ---- compute: lane -> row, warp -> role ----
    if (lane < nvalid) {
        float* srow = rows + lane * RROW;
        float R[9], T[3];

        if (wid == 0) {            // role A
            fk_root(srow, xoff, R, T, true);
            fk_step(srow, xoff, 1,  R, T, true);
            fk_step(srow, xoff, 4,  R, T, true);
            fk_step(srow, xoff, 7,  R, T, true);
            fk_step(srow, xoff, 10, R, T, true);
            fk_root(srow, xoff, R, T, false);   // recompute root (no checkpoint regs)
            fk_step(srow, xoff, 2,  R, T, true);
            fk_step(srow, xoff, 5,  R, T, true);
            fk_step(srow, xoff, 8,  R, T, true);
            fk_step(srow, xoff, 11, R, T, true);
        } else if (wid == 1) {     // role B
            fk_root(srow, xoff, R, T, false);
            fk_step(srow, xoff, 3,  R, T, true);
            fk_step(srow, xoff, 6,  R, T, true);
            fk_step(srow, xoff, 9,  R, T, true);
            fk_step(srow, xoff, 12, R, T, true);
            fk_step(srow, xoff, 15, R, T, true);
        } else if (wid == 2) {     // role C
            fk_root(srow, xoff, R, T, false);
            fk_step(srow, xoff, 3,  R, T, false);
            fk_step(srow, xoff, 6,  R, T, false);
            fk_step(srow, xoff, 9,  R, T, false);
            fk_step(srow, xoff, 13, R, T, true);
            fk_step(srow, xoff, 16, R, T, true);
            fk_step(srow, xoff, 18, R, T, true);
            fk_step(srow, xoff, 20, R, T, true);
            fk_step(srow, xoff, 22, R, T, true);
        } else {                   // role D
            fk_root(srow, xoff, R, T, false);
            fk_step(srow, xoff, 3,  R, T, false);
            fk_step(srow, xoff, 6,  R, T, false);
            fk_step(srow, xoff, 9,  R, T, false);
            fk_step(srow, xoff, 14, R, T, true);
            fk_step(srow, xoff, 17, R, T, true);
            fk_step(srow, xoff, 19, R, T, true);
            fk_step(srow, xoff, 21, R, T, true);
            fk_step(srow, xoff, 23, R, T, true);
        }
    }
    __syncthreads();

    // ---- coalesced store: 32 rows x 18 float4, gather from slots ----
    {
        float4* __restrict__ o4 =
            reinterpret_cast<float4*>(out) + (size_t)b0 * 18;
        const int total4 = nvalid * 18;
#pragma unroll
        for (int it = 0; it < 5; it++) {
            int idx = it * TPB + t;
            if (idx < total4) {
                int row = idx / 18;
                int j   = (idx % 18) * 4;
                const float* srow = rows + row * RROW;
                float v[4];
#pragma unroll
                for (int q = 0; q < 4; q++) {
                    int jj = j + q;
                    int c  = jj / 3;
                    int k  = jj - c * 3;
                    int base = (c <= 9 && (c % 3) == 0) ? (144 + c) : (c * 6);
                    v[q] = srow[base + k];
                }
                float4 o;
                o.x = v[0]; o.y = v[1]; o.z = v[2]; o.w = v[3];
                o4[idx] = o;
            }
        }
    }
}

extern "C" void kernel_launch(void* const* d_in, const int* in_sizes, int n_in,
                              void* d_out, int out_size) {
    const float* angles = (const float*)d_in[0];
    const float* xyz    = (const float*)d_in[1];
    float* out          = (float*)d_out;
    const int B = in_sizes[0] / (24 * 6);
    const int blocks = (B + ROWS - 1) / ROWS;
    skeleton_fk_kernel<<<blocks, TPB>>>(angles, xyz, out, B);
}